// round 10
// baseline (speedup 1.0000x reference)
#include <cuda_runtime.h>
#include <cuda_bf16.h>
#include <math.h>
#include <stdint.h>

#define B_   32
#define NN   511
#define F_   512
#define NP   255
#define NC   2048   // fused output width: [iou(1536) | f(512)]
#define KS   1024   // split activation width: [hi(512) | lo(512)]

// ---------------- scratch (static device memory) ----------------
__device__ __align__(16) float g_enode [B_*F_];
__device__ __align__(16) float g_eforw [B_*F_];
__device__ __align__(16) float g_logits[B_*NN];
__device__ __align__(16) float g_h     [B_*NN*F_];
__device__ __align__(16) float g_c     [B_*NN*F_];
__device__ __align__(16) float g_feiou [(size_t)B_*NN*NC];
__device__ __align__(16) float g_lvl   [(size_t)B_*256*NC];
__device__ __align__(16) __nv_bfloat16 g_f2s   [(size_t)B_*NN*KS];
__device__ __align__(16) __nv_bfloat16 g_hsplit[(size_t)B_*NN*KS];
__device__ __align__(16) __nv_bfloat16 g_wfe   [(size_t)NC*KS];
__device__ __align__(16) __nv_bfloat16 g_wu    [(size_t)NC*KS];
__device__ __align__(16) float g_biascat[NC];

__device__ __forceinline__ float sigm(float x) { return 1.f / (1.f + expf(-x)); }
__device__ __forceinline__ uint32_t smem_u32(const void* p) {
    uint32_t a;
    asm("{ .reg .u64 t; cvta.to.shared.u64 t, %1; cvt.u32.u64 %0, t; }" : "=r"(a) : "l"(p));
    return a;
}
#define SWZ(o) ((o) ^ (((o) >> 3) & 0x70))
#define CP16(d, s) asm volatile("cp.async.cg.shared.global [%0], [%1], 16;" :: "r"(d), "l"(s))
#define CP_COMMIT() asm volatile("cp.async.commit_group;")
#define CP_WAIT(n)  asm volatile("cp.async.wait_group %0;" :: "n"(n))

__device__ __forceinline__ void ldmx4(uint32_t* r, uint32_t addr) {
    asm volatile("ldmatrix.sync.aligned.m8n8.x4.shared.b16 {%0,%1,%2,%3}, [%4];"
                 : "=r"(r[0]), "=r"(r[1]), "=r"(r[2]), "=r"(r[3]) : "r"(addr));
}
__device__ __forceinline__ void mma16816(float* d, const uint32_t* a, const uint32_t* b) {
    asm volatile("mma.sync.aligned.m16n8k16.row.col.f32.bf16.bf16.f32 "
                 "{%0,%1,%2,%3}, {%4,%5,%6,%7}, {%8,%9}, {%0,%1,%2,%3};"
                 : "+f"(d[0]), "+f"(d[1]), "+f"(d[2]), "+f"(d[3])
                 : "r"(a[0]), "r"(a[1]), "r"(a[2]), "r"(a[3]), "r"(b[0]), "r"(b[1]));
}

// ================= all weights split in ONE launch ================
__global__ void wsplit_all(const float* __restrict__ Wfeiou, const float* __restrict__ Wfef,
                           const float* __restrict__ Wuiou,  const float* __restrict__ Wuf,
                           __nv_bfloat16* __restrict__ Ofe, __nv_bfloat16* __restrict__ Ou,
                           const float* __restrict__ b_iou, const float* __restrict__ b_f,
                           float* __restrict__ bias) {
    int idx = blockIdx.x * blockDim.x + threadIdx.x;
    if (idx < NC) bias[idx] = (idx < 1536) ? b_iou[idx] : b_f[idx - 1536];
    if (idx >= 2 * NC * 512) return;
    int which = idx >= NC * 512;
    int rem = which ? idx - NC * 512 : idx;
    int r = rem >> 9, k = rem & 511;
    const float* W = which ? (r < 1536 ? Wuiou : Wuf) : (r < 1536 ? Wfeiou : Wfef);
    int rl = (r < 1536) ? r : r - 1536;
    float v = W[(size_t)rl * 512 + k];
    __nv_bfloat16 hi = __float2bfloat16_rn(v);
    __nv_bfloat16 lo = __float2bfloat16_rn(v - __bfloat162float(hi));
    __nv_bfloat16* O = which ? Ou : Ofe;
    O[(size_t)r * KS + k]       = hi;
    O[(size_t)r * KS + 512 + k] = lo;
}

// ================= bf16 HMMA GEMM: 128x256 tile, 8 warps @ 64x64 =================
// C[M,2048] = gather(As)[M,K'=1536] @ Wc^T. K' chunks c=0..23 of 64.
// segment c>>3 selects A part {hi,lo,hi}, W part {hi,hi,lo}.
// gridDim.z>1 => split-K: z handles chunks [z*24/gz, ...), epilogue atomicAdd (C pre-zeroed).
struct GP {
    const __nv_bfloat16* As; const __nv_bfloat16* Wc; const float* bias; float* C;
    int M, rows, base;
};

#define ASTG 16384
#define BSTG 32768
#define STG_BYTES (ASTG + BSTG)
#define NSTAGE 3
#define GSMEM (NSTAGE * STG_BYTES + 1024)

__global__ void __launch_bounds__(256, 1) gemm_bf16(GP g) {
    extern __shared__ char smem_dyn[];
    const int tileN = blockIdx.x * 256;
    const int tileM = blockIdx.y * 128;
    if (tileM >= g.M) return;

    const uint32_t sb0 = smem_u32(smem_dyn);
    const uint32_t ab  = (sb0 + 1023u) & ~1023u;
    const int tid = threadIdx.x;
    const int wid = tid >> 5, lane = tid & 31;
    const int mw = (wid & 1) * 64;        // warp M offset (2)
    const int nw = (wid >> 1) * 64;       // warp N offset (4)

    // A fill: 2 threads per row (rows 0..127), 4x16B each
    const int a_row = tid >> 1;
    const int a_c   = (tid & 1) * 4;
    int row_g = tileM + a_row; if (row_g >= g.M) row_g = g.M - 1;
    int bb = row_g / g.rows, node = g.base + row_g % g.rows;
    const __nv_bfloat16* srcA = g.As + (size_t)(bb * NN + node) * KS;
    // B fill: 1 thread per row (rows 0..255), 8x16B each
    const __nv_bfloat16* srcB = g.Wc + (size_t)(tileN + tid) * KS;

    const int gz = gridDim.z;
    const int nt = 24 / gz;
    const int kBase = blockIdx.z * nt;

    auto issue = [&](int c, int buf) {
        const int segsel = c >> 3;
        const int aseg = (segsel == 1) ? 512 : 0;
        const int bseg = (segsel == 2) ? 512 : 0;
        const int kb = (c & 7) * 64;
        const uint32_t sA = ab + buf * STG_BYTES;
        const uint32_t sB = sA + ASTG;
        #pragma unroll
        for (int s = 0; s < 4; s++) {
            int cs = a_c + s;
            CP16(sA + SWZ(a_row * 128 + cs * 16), srcA + aseg + kb + cs * 8);
        }
        #pragma unroll
        for (int s = 0; s < 8; s++) {
            CP16(sB + SWZ(tid * 128 + s * 16), srcB + bseg + kb + s * 8);
        }
        CP_COMMIT();
    };

    float acc[4][8][4] = {};
    const int a_r = lane & 15, a_q = (lane >> 4) * 16;
    // B ldmx4: two n8-groups per instr
    const int b_r = ((lane >> 4) << 3) + (lane & 7);
    const int b_q = ((lane >> 3) & 1) * 16;

    issue(kBase + 0, 0);
    issue(kBase + 1, 1);
    for (int t = 0; t < nt; t++) {
        if (t + 1 < nt) CP_WAIT(1); else CP_WAIT(0);
        __syncthreads();
        const uint32_t sAb = ab + (t % NSTAGE) * STG_BYTES;
        const uint32_t sBb = sAb + ASTG;
        #pragma unroll
        for (int ks = 0; ks < 4; ks++) {
            uint32_t af[4][4], bf[8][2];
            #pragma unroll
            for (int mi = 0; mi < 4; mi++)
                ldmx4(af[mi], sAb + SWZ((mw + mi * 16 + a_r) * 128 + ks * 32 + a_q));
            #pragma unroll
            for (int nq = 0; nq < 4; nq++) {
                uint32_t r4[4];
                ldmx4(r4, sBb + SWZ((nw + nq * 16 + b_r) * 128 + ks * 32 + b_q));
                bf[nq * 2][0] = r4[0]; bf[nq * 2][1] = r4[1];
                bf[nq * 2 + 1][0] = r4[2]; bf[nq * 2 + 1][1] = r4[3];
            }
            #pragma unroll
            for (int mi = 0; mi < 4; mi++)
                #pragma unroll
                for (int ni = 0; ni < 8; ni++)
                    mma16816(acc[mi][ni], af[mi], bf[ni]);
        }
        if (t + 2 < nt) issue(kBase + t + 2, (t + 2) % NSTAGE);
    }

    // ---- epilogue ----
    const bool splitk = (gz > 1);
    #pragma unroll
    for (int mi = 0; mi < 4; mi++) {
        #pragma unroll
        for (int ni = 0; ni < 8; ni++) {
            int m0 = tileM + mw + mi * 16 + (lane >> 2);
            int n0 = tileN + nw + ni * 8 + (lane & 3) * 2;
            if (splitk) {
                float* c0 = g.C + (size_t)m0 * NC + n0;
                if (m0 < g.M) {
                    atomicAdd(c0, acc[mi][ni][0]);
                    atomicAdd(c0 + 1, acc[mi][ni][1]);
                }
                if (m0 + 8 < g.M) {
                    atomicAdd(c0 + 8 * NC, acc[mi][ni][2]);
                    atomicAdd(c0 + 8 * NC + 1, acc[mi][ni][3]);
                }
            } else {
                float b0 = 0.f, b1 = 0.f;
                if (g.bias) { b0 = g.bias[n0]; b1 = g.bias[n0 + 1]; }
                if (m0 < g.M)
                    *(float2*)(g.C + (size_t)m0 * NC + n0) =
                        make_float2(acc[mi][ni][0] + b0, acc[mi][ni][1] + b1);
                if (m0 + 8 < g.M)
                    *(float2*)(g.C + (size_t)(m0 + 8) * NC + n0) =
                        make_float2(acc[mi][ni][2] + b0, acc[mi][ni][3] + b1);
            }
        }
    }
}

// ================= non-GEMM kernels =================
__global__ void eh_proj_kernel(const float* __restrict__ eh, const float* __restrict__ Wn,
                               const float* __restrict__ Wf, float* __restrict__ en,
                               float* __restrict__ ef) {
    int gw   = (blockIdx.x * blockDim.x + threadIdx.x) >> 5;
    int lane = threadIdx.x & 31;
    if (gw >= 2 * B_ * F_) return;
    int which = (gw >= B_ * F_);
    int rem   = which ? gw - B_ * F_ : gw;
    int b = rem >> 9, f = rem & 511;
    const float4* w4 = (const float4*)((which ? Wf : Wn) + (size_t)f * 1024);
    const float4* e4 = (const float4*)(eh + (size_t)b * 1024);
    float s = 0.f;
    for (int k = lane; k < 256; k += 32) {
        float4 a = w4[k], c = e4[k];
        s += a.x * c.x + a.y * c.y + a.z * c.z + a.w * c.w;
    }
    #pragma unroll
    for (int o = 16; o; o >>= 1) s += __shfl_down_sync(0xffffffffu, s, o);
    if (!lane) (which ? ef : en)[rem] = s;
}

__global__ void dot_kernel(const float* __restrict__ X, const float* __restrict__ v,
                           float* __restrict__ out) {
    int gw   = (blockIdx.x * blockDim.x + threadIdx.x) >> 5;
    int lane = threadIdx.x & 31;
    if (gw >= B_ * NN) return;
    int b = gw / NN;
    const float4* x4 = (const float4*)(X + (size_t)gw * F_);
    const float4* v4 = (const float4*)(v + (size_t)b * F_);
    float s = 0.f;
    #pragma unroll
    for (int k = lane; k < 128; k += 32) {
        float4 a = x4[k], c = v4[k];
        s += a.x * c.x + a.y * c.y + a.z * c.z + a.w * c.w;
    }
    #pragma unroll
    for (int o = 16; o; o >>= 1) s += __shfl_down_sync(0xffffffffu, s, o);
    if (!lane) out[gw] = s;
}

__global__ void feat2s_kernel(const float* __restrict__ feat, const float* __restrict__ en,
                              __nv_bfloat16* __restrict__ o) {
    int bi = blockIdx.x;
    int b = bi / NN, i = bi % NN;
    int cnt = min(i + 3, NN - 1) - i + 1;
    __shared__ float sw[4];
    int t = threadIdx.x;
    int wj = t >> 5, lane = t & 31;
    if (wj < cnt) {
        const float4* x4 = (const float4*)(feat + ((size_t)bi + wj) * F_);
        const float4* v4 = (const float4*)(en + (size_t)b * F_);
        float s = 0.f;
        #pragma unroll
        for (int k = lane; k < 128; k += 32) {
            float4 a = x4[k], c = v4[k];
            s += a.x * c.x + a.y * c.y + a.z * c.z + a.w * c.w;
        }
        #pragma unroll
        for (int off = 16; off; off >>= 1) s += __shfl_down_sync(0xffffffffu, s, off);
        if (!lane) sw[wj] = s;
    }
    __syncthreads();
    float w[4];
    float mx = -1e30f;
    for (int j = 0; j < cnt; j++) { w[j] = sw[j]; mx = fmaxf(mx, w[j]); }
    float ssum = 0.f;
    for (int j = 0; j < cnt; j++) { w[j] = expf(w[j] - mx); ssum += w[j]; }
    float inv = 1.f / ssum;
    const float4* base = (const float4*)(feat + (size_t)bi * F_);
    __nv_bfloat16* orow = o + (size_t)bi * KS;
    {
        int f = t;
        float4 a = make_float4(0.f, 0.f, 0.f, 0.f);
        for (int j = 0; j < cnt; j++) {
            float4 v = base[j * 128 + f];
            a.x += w[j] * v.x; a.y += w[j] * v.y; a.z += w[j] * v.z; a.w += w[j] * v.w;
        }
        a.x *= inv; a.y *= inv; a.z *= inv; a.w *= inv;
        __nv_bfloat16 h0 = __float2bfloat16_rn(a.x), h1 = __float2bfloat16_rn(a.y);
        __nv_bfloat16 h2 = __float2bfloat16_rn(a.z), h3 = __float2bfloat16_rn(a.w);
        orow[f * 4 + 0] = h0; orow[f * 4 + 1] = h1; orow[f * 4 + 2] = h2; orow[f * 4 + 3] = h3;
        orow[512 + f * 4 + 0] = __float2bfloat16_rn(a.x - __bfloat162float(h0));
        orow[512 + f * 4 + 1] = __float2bfloat16_rn(a.y - __bfloat162float(h1));
        orow[512 + f * 4 + 2] = __float2bfloat16_rn(a.z - __bfloat162float(h2));
        orow[512 + f * 4 + 3] = __float2bfloat16_rn(a.w - __bfloat162float(h3));
    }
}

__device__ __forceinline__ void write_h_split(__nv_bfloat16* hs, size_t row, int f4, float4 hn) {
    __nv_bfloat16* p = hs + row * KS;
    __nv_bfloat16 h0 = __float2bfloat16_rn(hn.x), h1 = __float2bfloat16_rn(hn.y);
    __nv_bfloat16 h2 = __float2bfloat16_rn(hn.z), h3 = __float2bfloat16_rn(hn.w);
    p[f4 * 4 + 0] = h0; p[f4 * 4 + 1] = h1; p[f4 * 4 + 2] = h2; p[f4 * 4 + 3] = h3;
    p[512 + f4 * 4 + 0] = __float2bfloat16_rn(hn.x - __bfloat162float(h0));
    p[512 + f4 * 4 + 1] = __float2bfloat16_rn(hn.y - __bfloat162float(h1));
    p[512 + f4 * 4 + 2] = __float2bfloat16_rn(hn.z - __bfloat162float(h2));
    p[512 + f4 * 4 + 3] = __float2bfloat16_rn(hn.w - __bfloat162float(h3));
}

__global__ void leaf_kernel(const float* __restrict__ feiou, float* __restrict__ h,
                            float* __restrict__ c, __nv_bfloat16* __restrict__ hs) {
    size_t idx = (size_t)blockIdx.x * blockDim.x + threadIdx.x;
    if (idx >= (size_t)B_ * 256 * 128) return;
    int f4 = (int)(idx & 127);
    size_t t = idx >> 7;
    int node = 255 + (int)(t % 256);
    int b = (int)(t / 256);
    size_t row = (size_t)b * NN + node;
    const float4* r = (const float4*)(feiou + row * NC);
    float4 ig = r[f4], og = r[128 + f4], ug = r[256 + f4];
    float4 cn, hn;
    cn.x = sigm(ig.x) * fmaxf(ug.x, 0.f); hn.x = sigm(og.x) * tanhf(cn.x);
    cn.y = sigm(ig.y) * fmaxf(ug.y, 0.f); hn.y = sigm(og.y) * tanhf(cn.y);
    cn.z = sigm(ig.z) * fmaxf(ug.z, 0.f); hn.z = sigm(og.z) * tanhf(cn.z);
    cn.w = sigm(ig.w) * fmaxf(ug.w, 0.f); hn.w = sigm(og.w) * tanhf(cn.w);
    ((float4*)(c + row * F_))[f4] = cn;
    ((float4*)(h + row * F_))[f4] = hn;
    write_h_split(hs, row, f4, hn);
}

__global__ void combine_kernel(const float* __restrict__ lvl, const float* __restrict__ feiou,
                               float* __restrict__ h, float* __restrict__ c,
                               __nv_bfloat16* __restrict__ hs, int start, int cnt) {
    size_t idx = (size_t)blockIdx.x * blockDim.x + threadIdx.x;
    if (idx >= (size_t)B_ * cnt * 128) return;
    int f4 = (int)(idx & 127);
    size_t t = idx >> 7;
    int q = (int)(t % cnt);
    int b = (int)(t / cnt);
    int p = start + q;
    size_t prow = (size_t)b * NN + p;
    const float4* tL = (const float4*)(lvl + ((size_t)b * 2 * cnt + 2 * q) * NC);
    const float4* tR = tL + (NC / 4);
    const float4* fi = (const float4*)(feiou + prow * NC);
    float4 igL = tL[f4],       igR = tR[f4],       ig2 = fi[f4];
    float4 ogL = tL[128 + f4], ogR = tR[128 + f4], og2 = fi[128 + f4];
    float4 ugL = tL[256 + f4], ugR = tR[256 + f4], ug2 = fi[256 + f4];
    float4 fe  = fi[384 + f4];
    float4 fl  = tL[384 + f4], fr = tR[384 + f4];
    size_t cl = ((size_t)b * NN + 2 * p + 1) * F_;
    float4 cL = ((const float4*)(c + cl))[f4];
    float4 cR = ((const float4*)(c + cl + F_))[f4];
    float4 cn, hn;
    {
        float ig = igL.x + igR.x + ig2.x, og = ogL.x + ogR.x + og2.x, ug = ugL.x + ugR.x + ug2.x;
        float cs = sigm(fl.x + fe.x) * cL.x + sigm(fr.x + fe.x) * cR.x;
        cn.x = sigm(ig) * fmaxf(ug, 0.f) + cs; hn.x = sigm(og) * tanhf(cn.x);
        ig = igL.y + igR.y + ig2.y; og = ogL.y + ogR.y + og2.y; ug = ugL.y + ugR.y + ug2.y;
        cs = sigm(fl.y + fe.y) * cL.y + sigm(fr.y + fe.y) * cR.y;
        cn.y = sigm(ig) * fmaxf(ug, 0.f) + cs; hn.y = sigm(og) * tanhf(cn.y);
        ig = igL.z + igR.z + ig2.z; og = ogL.z + ogR.z + og2.z; ug = ugL.z + ugR.z + ug2.z;
        cs = sigm(fl.z + fe.z) * cL.z + sigm(fr.z + fe.z) * cR.z;
        cn.z = sigm(ig) * fmaxf(ug, 0.f) + cs; hn.z = sigm(og) * tanhf(cn.z);
        ig = igL.w + igR.w + ig2.w; og = ogL.w + ogR.w + og2.w; ug = ugL.w + ugR.w + ug2.w;
        cs = sigm(fl.w + fe.w) * cL.w + sigm(fr.w + fe.w) * cR.w;
        cn.w = sigm(ig) * fmaxf(ug, 0.f) + cs; hn.w = sigm(og) * tanhf(cn.w);
    }
    ((float4*)(c + prow * F_))[f4] = cn;
    ((float4*)(h + prow * F_))[f4] = hn;
    write_h_split(hs, prow, f4, hn);
}

__global__ void final_kernel(const float* __restrict__ logits, const float* __restrict__ h,
                             float* __restrict__ out) {
    int b = blockIdx.x;
    int t = threadIdx.x;
    __shared__ float sp[512];
    __shared__ float red[17];
    float l = (t < NN) ? logits[b * NN + t] : -1e30f;
    float m = l;
    #pragma unroll
    for (int o = 16; o; o >>= 1) m = fmaxf(m, __shfl_xor_sync(0xffffffffu, m, o));
    if ((t & 31) == 0) red[t >> 5] = m;
    __syncthreads();
    if (t == 0) {
        float mm = red[0];
        for (int i = 1; i < 16; i++) mm = fmaxf(mm, red[i]);
        red[16] = mm;
    }
    __syncthreads();
    float mx = red[16];
    float e = (t < NN) ? expf(l - mx) : 0.f;
    sp[t] = e;
    float s = e;
    #pragma unroll
    for (int o = 16; o; o >>= 1) s += __shfl_xor_sync(0xffffffffu, s, o);
    __syncthreads();
    if ((t & 31) == 0) red[t >> 5] = s;
    __syncthreads();
    if (t == 0) {
        float ss = 0.f;
        for (int i = 0; i < 16; i++) ss += red[i];
        red[16] = 1.f / ss;
    }
    __syncthreads();
    float inv = red[16];
    const float* hb = h + (size_t)b * NN * F_;
    float acc = 0.f;
    for (int i = 0; i < NN; i++) acc += sp[i] * hb[(size_t)i * F_ + t];
    out[b * F_ + t] = acc * inv;
}

// ================= launch =================
extern "C" void kernel_launch(void* const* d_in, const int* in_sizes, int n_in,
                              void* d_out, int out_size) {
    const float* features   = (const float*)d_in[0];
    const float* eh         = (const float*)d_in[5];
    const float* Wn         = (const float*)d_in[6];
    const float* Wf         = (const float*)d_in[7];
    const float* W_U_iou    = (const float*)d_in[8];
    const float* W_U_fe_iou = (const float*)d_in[9];
    const float* b_U_fe_iou = (const float*)d_in[10];
    const float* W_U_f      = (const float*)d_in[11];
    const float* W_U_fe_f   = (const float*)d_in[12];
    const float* b_U_fe_f   = (const float*)d_in[13];
    float* out = (float*)d_out;

    float *p_en, *p_ef, *p_lg, *p_h, *p_c, *p_feiou, *p_lvl, *p_bias;
    __nv_bfloat16 *p_f2s, *p_hs, *p_wfe, *p_wu;
    cudaGetSymbolAddress((void**)&p_en,    g_enode);
    cudaGetSymbolAddress((void**)&p_ef,    g_eforw);
    cudaGetSymbolAddress((void**)&p_lg,    g_logits);
    cudaGetSymbolAddress((void**)&p_h,     g_h);
    cudaGetSymbolAddress((void**)&p_c,     g_c);
    cudaGetSymbolAddress((void**)&p_feiou, g_feiou);
    cudaGetSymbolAddress((void**)&p_lvl,   g_lvl);
    cudaGetSymbolAddress((void**)&p_bias,  g_biascat);
    cudaGetSymbolAddress((void**)&p_f2s,   g_f2s);
    cudaGetSymbolAddress((void**)&p_hs,    g_hsplit);
    cudaGetSymbolAddress((void**)&p_wfe,   g_wfe);
    cudaGetSymbolAddress((void**)&p_wu,    g_wu);

    static int smem_set = 0;
    if (!smem_set) {
        cudaFuncSetAttribute(gemm_bf16, cudaFuncAttributeMaxDynamicSharedMemorySize, GSMEM);
        smem_set = 1;
    }

    // 0) split all weights + bias
    wsplit_all<<<(2 * NC * 512 + 255) / 256, 256>>>(W_U_fe_iou, W_U_fe_f, W_U_iou, W_U_f,
                                                    p_wfe, p_wu, b_U_fe_iou, b_U_fe_f, p_bias);
    // 1) eh projections + fused attention
    eh_proj_kernel<<<(2 * B_ * F_ * 32 + 255) / 256, 256>>>(eh, Wn, Wf, p_en, p_ef);
    feat2s_kernel<<<B_ * NN, 128>>>(features, p_en, p_f2s);
    // 2) fused fe GEMM
    {
        GP g = { p_f2s, p_wfe, p_bias, p_feiou, B_ * NN, NN, 0 };
        dim3 grid(NC / 256, (B_ * NN + 127) / 128, 1);
        gemm_bf16<<<grid, 256, GSMEM>>>(g);
    }
    // 3) leaves
    leaf_kernel<<<(B_ * 256 * 128 + 255) / 256, 256>>>(p_feiou, p_h, p_c, p_hs);
    // 4) levels bottom-up
    for (int n = 1; n <= 8; n++) {
        int cnt = 1 << (8 - n);
        int start = cnt - 1;
        int rows = 2 * cnt;
        int M = B_ * rows;
        GP g = { p_hs, p_wu, nullptr, p_lvl, M, rows, 2 * start + 1 };
        int gz = (M <= 2048) ? 3 : 1;
        if (gz > 1) cudaMemsetAsync(p_lvl, 0, (size_t)M * NC * sizeof(float), 0);
        dim3 grid(NC / 256, (M + 127) / 128, gz);
        gemm_bf16<<<grid, 256, GSMEM>>>(g);
        combine_kernel<<<(B_ * cnt * 128 + 255) / 256, 256>>>(p_lvl, p_feiou,
                                                              p_h, p_c, p_hs, start, cnt);
    }
    // 5) output pooling
    dot_kernel<<<(B_ * NN * 32 + 255) / 256, 256>>>(p_h, p_ef, p_lg);
    final_kernel<<<B_, F_>>>(p_lg, p_h, out);
}

// round 12
// speedup vs baseline: 1.1859x; 1.1859x over previous
#include <cuda_runtime.h>
#include <cuda_bf16.h>
#include <math.h>
#include <stdint.h>

#define B_   32
#define NN   511
#define F_   512
#define NP   255
#define NC   2048   // fused output width: [iou(1536) | f(512)]
#define KS   1024   // split activation width: [hi(512) | lo(512)]

// ---------------- scratch (static device memory) ----------------
__device__ __align__(16) float g_enode [B_*F_];
__device__ __align__(16) float g_eforw [B_*F_];
__device__ __align__(16) float g_logits[B_*NN];
__device__ __align__(16) float g_h     [B_*NN*F_];
__device__ __align__(16) float g_c     [B_*NN*F_];
__device__ __align__(16) float g_feiou [(size_t)B_*NN*NC];
__device__ __align__(16) float g_lvl   [(size_t)B_*256*NC];   // also holds split-K slices
__device__ __align__(16) __nv_bfloat16 g_f2s   [(size_t)B_*NN*KS];
__device__ __align__(16) __nv_bfloat16 g_hsplit[(size_t)B_*NN*KS];
__device__ __align__(16) __nv_bfloat16 g_wfe   [(size_t)NC*KS];
__device__ __align__(16) __nv_bfloat16 g_wu    [(size_t)NC*KS];
__device__ __align__(16) float g_biascat[NC];

__device__ __forceinline__ float sigm(float x) { return 1.f / (1.f + expf(-x)); }
__device__ __forceinline__ uint32_t smem_u32(const void* p) {
    uint32_t a;
    asm("{ .reg .u64 t; cvta.to.shared.u64 t, %1; cvt.u32.u64 %0, t; }" : "=r"(a) : "l"(p));
    return a;
}
#define SWZ(o) ((o) ^ (((o) >> 3) & 0x70))
#define CP16(d, s) asm volatile("cp.async.cg.shared.global [%0], [%1], 16;" :: "r"(d), "l"(s))
#define CP_COMMIT() asm volatile("cp.async.commit_group;")
#define CP_WAIT(n)  asm volatile("cp.async.wait_group %0;" :: "n"(n))

__device__ __forceinline__ void ldmx4(uint32_t* r, uint32_t addr) {
    asm volatile("ldmatrix.sync.aligned.m8n8.x4.shared.b16 {%0,%1,%2,%3}, [%4];"
                 : "=r"(r[0]), "=r"(r[1]), "=r"(r[2]), "=r"(r[3]) : "r"(addr));
}
__device__ __forceinline__ void ldmx2(uint32_t* r, uint32_t addr) {
    asm volatile("ldmatrix.sync.aligned.m8n8.x2.shared.b16 {%0,%1}, [%2];"
                 : "=r"(r[0]), "=r"(r[1]) : "r"(addr));
}
__device__ __forceinline__ void mma16816(float* d, const uint32_t* a, const uint32_t* b) {
    asm volatile("mma.sync.aligned.m16n8k16.row.col.f32.bf16.bf16.f32 "
                 "{%0,%1,%2,%3}, {%4,%5,%6,%7}, {%8,%9}, {%0,%1,%2,%3};"
                 : "+f"(d[0]), "+f"(d[1]), "+f"(d[2]), "+f"(d[3])
                 : "r"(a[0]), "r"(a[1]), "r"(a[2]), "r"(a[3]), "r"(b[0]), "r"(b[1]));
}
__device__ __forceinline__ void add4(float4& a, float4 b) {
    a.x += b.x; a.y += b.y; a.z += b.z; a.w += b.w;
}

// ================= all weights split in ONE launch ================
__global__ void wsplit_all(const float* __restrict__ Wfeiou, const float* __restrict__ Wfef,
                           const float* __restrict__ Wuiou,  const float* __restrict__ Wuf,
                           __nv_bfloat16* __restrict__ Ofe, __nv_bfloat16* __restrict__ Ou,
                           const float* __restrict__ b_iou, const float* __restrict__ b_f,
                           float* __restrict__ bias) {
    int idx = blockIdx.x * blockDim.x + threadIdx.x;
    if (idx < NC) bias[idx] = (idx < 1536) ? b_iou[idx] : b_f[idx - 1536];
    if (idx >= 2 * NC * 512) return;
    int which = idx >= NC * 512;
    int rem = which ? idx - NC * 512 : idx;
    int r = rem >> 9, k = rem & 511;
    const float* W = which ? (r < 1536 ? Wuiou : Wuf) : (r < 1536 ? Wfeiou : Wfef);
    int rl = (r < 1536) ? r : r - 1536;
    float v = W[(size_t)rl * 512 + k];
    __nv_bfloat16 hi = __float2bfloat16_rn(v);
    __nv_bfloat16 lo = __float2bfloat16_rn(v - __bfloat162float(hi));
    __nv_bfloat16* O = which ? Ou : Ofe;
    O[(size_t)r * KS + k]       = hi;
    O[(size_t)r * KS + 512 + k] = lo;
}

// ================= bf16 HMMA GEMM (R7 config): 128x128, 8 warps @ 64x32 ===========
// C row for output: outScatter ? (b*NN + node) : m   (m = b*rows + local)
// gridDim.z = gz > 1 => split-K into separate slices C + z*M*NC (no bias), compact rows.
struct GP {
    const __nv_bfloat16* As; const __nv_bfloat16* Wc; const float* bias; float* C;
    int M, rows, base, outScatter;
};

#define TILE_BYTES 16384
#define NSTAGE 3
#define GSMEM (NSTAGE * 2 * TILE_BYTES + 1024)

__global__ void __launch_bounds__(256) gemm_bf16(GP g) {
    extern __shared__ char smem_dyn[];
    const int tileN = blockIdx.x * 128;
    const int tileM = blockIdx.y * 128;
    if (tileM >= g.M) return;

    const uint32_t sb0 = smem_u32(smem_dyn);
    const uint32_t ab  = (sb0 + 1023u) & ~1023u;
    const int tid = threadIdx.x;
    const int wid = tid >> 5, lane = tid & 31;
    const int mw = (wid & 1) * 64;
    const int nw = (wid >> 1) * 32;

    const int row  = tid >> 1;
    const int c16b = (tid & 1) * 4;
    int row_g = tileM + row; if (row_g >= g.M) row_g = g.M - 1;
    int b = row_g / g.rows, node = g.base + row_g % g.rows;
    const __nv_bfloat16* srcA = g.As + (size_t)(b * NN + node) * KS;
    const __nv_bfloat16* srcB = g.Wc + (size_t)(tileN + row) * KS;

    const int gz = gridDim.z;
    const int nt = 24 / gz;
    const int kBase = blockIdx.z * nt;

    auto issue = [&](int c, int buf) {
        const int segsel = c >> 3;
        const int aseg = (segsel == 1) ? 512 : 0;
        const int bseg = (segsel == 2) ? 512 : 0;
        const int kb = (c & 7) * 64;
        const uint32_t sA = ab + buf * 2 * TILE_BYTES;
        const uint32_t sB = sA + TILE_BYTES;
        #pragma unroll
        for (int s = 0; s < 4; s++) {
            int cs = c16b + s;
            int eo = kb + cs * 8;
            CP16(sA + SWZ(row * 128 + cs * 16), srcA + aseg + eo);
            CP16(sB + SWZ(row * 128 + cs * 16), srcB + bseg + eo);
        }
        CP_COMMIT();
    };

    float acc[4][4][4] = {};
    const int a_r = lane & 15, a_q = (lane >> 4) * 16;
    const int b_r = lane & 7,  b_q = ((lane >> 3) & 1) * 16;

    issue(kBase + 0, 0);
    issue(kBase + 1, 1);
    for (int t = 0; t < nt; t++) {
        if (t + 1 < nt) CP_WAIT(1); else CP_WAIT(0);
        __syncthreads();
        const uint32_t sAb = ab + (t % NSTAGE) * 2 * TILE_BYTES;
        const uint32_t sBb = sAb + TILE_BYTES;
        #pragma unroll
        for (int ks = 0; ks < 4; ks++) {
            uint32_t af[4][4], bf[4][2];
            #pragma unroll
            for (int mi = 0; mi < 4; mi++)
                ldmx4(af[mi], sAb + SWZ((mw + mi * 16 + a_r) * 128 + ks * 32 + a_q));
            #pragma unroll
            for (int ni = 0; ni < 4; ni++)
                ldmx2(bf[ni], sBb + SWZ((nw + ni * 8 + b_r) * 128 + ks * 32 + b_q));
            #pragma unroll
            for (int mi = 0; mi < 4; mi++)
                #pragma unroll
                for (int ni = 0; ni < 4; ni++)
                    mma16816(acc[mi][ni], af[mi], bf[ni]);
        }
        if (t + 2 < nt) issue(kBase + t + 2, (t + 2) % NSTAGE);
    }

    float* Cout = g.C + (size_t)blockIdx.z * g.M * NC;
    const bool useBias = (g.bias != nullptr) && (gz == 1);
    #pragma unroll
    for (int mi = 0; mi < 4; mi++) {
        #pragma unroll
        for (int ni = 0; ni < 4; ni++) {
            int m0 = tileM + mw + mi * 16 + (lane >> 2);
            int n0 = tileN + nw + ni * 8 + (lane & 3) * 2;
            float b0 = 0.f, b1 = 0.f;
            if (useBias) { b0 = g.bias[n0]; b1 = g.bias[n0 + 1]; }
            #pragma unroll
            for (int half = 0; half < 2; half++) {
                int m = m0 + half * 8;
                if (m >= g.M) continue;
                size_t orow;
                if (g.outScatter) {
                    int ob = m / g.rows, on = g.base + m % g.rows;
                    orow = (size_t)ob * NN + on;
                } else {
                    orow = (size_t)m;
                }
                *(float2*)(Cout + orow * NC + n0) =
                    make_float2(acc[mi][ni][half * 2] + b0, acc[mi][ni][half * 2 + 1] + b1);
            }
        }
    }
}

// ================= non-GEMM kernels =================
__global__ void eh_proj_kernel(const float* __restrict__ eh, const float* __restrict__ Wn,
                               const float* __restrict__ Wf, float* __restrict__ en,
                               float* __restrict__ ef) {
    int gw   = (blockIdx.x * blockDim.x + threadIdx.x) >> 5;
    int lane = threadIdx.x & 31;
    if (gw >= 2 * B_ * F_) return;
    int which = (gw >= B_ * F_);
    int rem   = which ? gw - B_ * F_ : gw;
    int b = rem >> 9, f = rem & 511;
    const float4* w4 = (const float4*)((which ? Wf : Wn) + (size_t)f * 1024);
    const float4* e4 = (const float4*)(eh + (size_t)b * 1024);
    float s = 0.f;
    for (int k = lane; k < 256; k += 32) {
        float4 a = w4[k], c = e4[k];
        s += a.x * c.x + a.y * c.y + a.z * c.z + a.w * c.w;
    }
    #pragma unroll
    for (int o = 16; o; o >>= 1) s += __shfl_down_sync(0xffffffffu, s, o);
    if (!lane) (which ? ef : en)[rem] = s;
}

__global__ void dot_kernel(const float* __restrict__ X, const float* __restrict__ v,
                           float* __restrict__ out) {
    int gw   = (blockIdx.x * blockDim.x + threadIdx.x) >> 5;
    int lane = threadIdx.x & 31;
    if (gw >= B_ * NN) return;
    int b = gw / NN;
    const float4* x4 = (const float4*)(X + (size_t)gw * F_);
    const float4* v4 = (const float4*)(v + (size_t)b * F_);
    float s = 0.f;
    #pragma unroll
    for (int k = lane; k < 128; k += 32) {
        float4 a = x4[k], c = v4[k];
        s += a.x * c.x + a.y * c.y + a.z * c.z + a.w * c.w;
    }
    #pragma unroll
    for (int o = 16; o; o >>= 1) s += __shfl_down_sync(0xffffffffu, s, o);
    if (!lane) out[gw] = s;
}

__global__ void feat2s_kernel(const float* __restrict__ feat, const float* __restrict__ en,
                              __nv_bfloat16* __restrict__ o) {
    int bi = blockIdx.x;
    int b = bi / NN, i = bi % NN;
    int cnt = min(i + 3, NN - 1) - i + 1;
    __shared__ float sw[4];
    int t = threadIdx.x;
    int wj = t >> 5, lane = t & 31;
    if (wj < cnt) {
        const float4* x4 = (const float4*)(feat + ((size_t)bi + wj) * F_);
        const float4* v4 = (const float4*)(en + (size_t)b * F_);
        float s = 0.f;
        #pragma unroll
        for (int k = lane; k < 128; k += 32) {
            float4 a = x4[k], c = v4[k];
            s += a.x * c.x + a.y * c.y + a.z * c.z + a.w * c.w;
        }
        #pragma unroll
        for (int off = 16; off; off >>= 1) s += __shfl_down_sync(0xffffffffu, s, off);
        if (!lane) sw[wj] = s;
    }
    __syncthreads();
    float w[4];
    float mx = -1e30f;
    for (int j = 0; j < cnt; j++) { w[j] = sw[j]; mx = fmaxf(mx, w[j]); }
    float ssum = 0.f;
    for (int j = 0; j < cnt; j++) { w[j] = expf(w[j] - mx); ssum += w[j]; }
    float inv = 1.f / ssum;
    const float4* base = (const float4*)(feat + (size_t)bi * F_);
    __nv_bfloat16* orow = o + (size_t)bi * KS;
    {
        int f = t;
        float4 a = make_float4(0.f, 0.f, 0.f, 0.f);
        for (int j = 0; j < cnt; j++) {
            float4 v = base[j * 128 + f];
            a.x += w[j] * v.x; a.y += w[j] * v.y; a.z += w[j] * v.z; a.w += w[j] * v.w;
        }
        a.x *= inv; a.y *= inv; a.z *= inv; a.w *= inv;
        __nv_bfloat16 h0 = __float2bfloat16_rn(a.x), h1 = __float2bfloat16_rn(a.y);
        __nv_bfloat16 h2 = __float2bfloat16_rn(a.z), h3 = __float2bfloat16_rn(a.w);
        orow[f * 4 + 0] = h0; orow[f * 4 + 1] = h1; orow[f * 4 + 2] = h2; orow[f * 4 + 3] = h3;
        orow[512 + f * 4 + 0] = __float2bfloat16_rn(a.x - __bfloat162float(h0));
        orow[512 + f * 4 + 1] = __float2bfloat16_rn(a.y - __bfloat162float(h1));
        orow[512 + f * 4 + 2] = __float2bfloat16_rn(a.z - __bfloat162float(h2));
        orow[512 + f * 4 + 3] = __float2bfloat16_rn(a.w - __bfloat162float(h3));
    }
}

__device__ __forceinline__ void write_h_split(__nv_bfloat16* hs, size_t row, int f4, float4 hn) {
    __nv_bfloat16* p = hs + row * KS;
    __nv_bfloat16 h0 = __float2bfloat16_rn(hn.x), h1 = __float2bfloat16_rn(hn.y);
    __nv_bfloat16 h2 = __float2bfloat16_rn(hn.z), h3 = __float2bfloat16_rn(hn.w);
    p[f4 * 4 + 0] = h0; p[f4 * 4 + 1] = h1; p[f4 * 4 + 2] = h2; p[f4 * 4 + 3] = h3;
    p[512 + f4 * 4 + 0] = __float2bfloat16_rn(hn.x - __bfloat162float(h0));
    p[512 + f4 * 4 + 1] = __float2bfloat16_rn(hn.y - __bfloat162float(h1));
    p[512 + f4 * 4 + 2] = __float2bfloat16_rn(hn.z - __bfloat162float(h2));
    p[512 + f4 * 4 + 3] = __float2bfloat16_rn(hn.w - __bfloat162float(h3));
}

__global__ void leaf_kernel(const float* __restrict__ feiou, float* __restrict__ h,
                            float* __restrict__ c, __nv_bfloat16* __restrict__ hs) {
    size_t idx = (size_t)blockIdx.x * blockDim.x + threadIdx.x;
    if (idx >= (size_t)B_ * 256 * 128) return;
    int f4 = (int)(idx & 127);
    size_t t = idx >> 7;
    int node = 255 + (int)(t % 256);
    int b = (int)(t / 256);
    size_t row = (size_t)b * NN + node;
    const float4* r = (const float4*)(feiou + row * NC);
    float4 ig = r[f4], og = r[128 + f4], ug = r[256 + f4];
    float4 cn, hn;
    cn.x = sigm(ig.x) * fmaxf(ug.x, 0.f); hn.x = sigm(og.x) * tanhf(cn.x);
    cn.y = sigm(ig.y) * fmaxf(ug.y, 0.f); hn.y = sigm(og.y) * tanhf(cn.y);
    cn.z = sigm(ig.z) * fmaxf(ug.z, 0.f); hn.z = sigm(og.z) * tanhf(cn.z);
    cn.w = sigm(ig.w) * fmaxf(ug.w, 0.f); hn.w = sigm(og.w) * tanhf(cn.w);
    ((float4*)(c + row * F_))[f4] = cn;
    ((float4*)(h + row * F_))[f4] = hn;
    write_h_split(hs, row, f4, hn);
}

// per-level combine: sums split-K slices and the two children's rows
__global__ void combine_kernel(const float* __restrict__ lvl, const float* __restrict__ feiou,
                               float* __restrict__ h, float* __restrict__ c,
                               __nv_bfloat16* __restrict__ hs, int start, int cnt,
                               int gz, size_t sstride) {
    size_t idx = (size_t)blockIdx.x * blockDim.x + threadIdx.x;
    if (idx >= (size_t)B_ * cnt * 128) return;
    int f4 = (int)(idx & 127);
    size_t t = idx >> 7;
    int q = (int)(t % cnt);
    int b = (int)(t / cnt);
    int p = start + q;
    size_t prow = (size_t)b * NN + p;
    const float* baseL = lvl + ((size_t)b * 2 * cnt + 2 * q) * NC;
    float4 s[8];
    #pragma unroll
    for (int i = 0; i < 8; i++) s[i] = make_float4(0.f, 0.f, 0.f, 0.f);
    for (int z = 0; z < gz; z++) {
        const float4* tL = (const float4*)(baseL + z * sstride);
        const float4* tR = tL + (NC / 4);
        add4(s[0], tL[f4]);       add4(s[1], tL[128 + f4]);
        add4(s[2], tL[256 + f4]); add4(s[3], tL[384 + f4]);
        add4(s[4], tR[f4]);       add4(s[5], tR[128 + f4]);
        add4(s[6], tR[256 + f4]); add4(s[7], tR[384 + f4]);
    }
    const float4* fi = (const float4*)(feiou + prow * NC);
    float4 ig2 = fi[f4], og2 = fi[128 + f4], ug2 = fi[256 + f4], fe = fi[384 + f4];
    size_t cl = ((size_t)b * NN + 2 * p + 1) * F_;
    float4 cL = ((const float4*)(c + cl))[f4];
    float4 cR = ((const float4*)(c + cl + F_))[f4];
    float4 cn, hn;
    {
        float ig = s[0].x + s[4].x + ig2.x, og = s[1].x + s[5].x + og2.x, ug = s[2].x + s[6].x + ug2.x;
        float cs = sigm(s[3].x + fe.x) * cL.x + sigm(s[7].x + fe.x) * cR.x;
        cn.x = sigm(ig) * fmaxf(ug, 0.f) + cs; hn.x = sigm(og) * tanhf(cn.x);
        ig = s[0].y + s[4].y + ig2.y; og = s[1].y + s[5].y + og2.y; ug = s[2].y + s[6].y + ug2.y;
        cs = sigm(s[3].y + fe.y) * cL.y + sigm(s[7].y + fe.y) * cR.y;
        cn.y = sigm(ig) * fmaxf(ug, 0.f) + cs; hn.y = sigm(og) * tanhf(cn.y);
        ig = s[0].z + s[4].z + ig2.z; og = s[1].z + s[5].z + og2.z; ug = s[2].z + s[6].z + ug2.z;
        cs = sigm(s[3].z + fe.z) * cL.z + sigm(s[7].z + fe.z) * cR.z;
        cn.z = sigm(ig) * fmaxf(ug, 0.f) + cs; hn.z = sigm(og) * tanhf(cn.z);
        ig = s[0].w + s[4].w + ig2.w; og = s[1].w + s[5].w + og2.w; ug = s[2].w + s[6].w + ug2.w;
        cs = sigm(s[3].w + fe.w) * cL.w + sigm(s[7].w + fe.w) * cR.w;
        cn.w = sigm(ig) * fmaxf(ug, 0.f) + cs; hn.w = sigm(og) * tanhf(cn.w);
    }
    ((float4*)(c + prow * F_))[f4] = cn;
    ((float4*)(h + prow * F_))[f4] = hn;
    write_h_split(hs, prow, f4, hn);
}

__global__ void final_kernel(const float* __restrict__ logits, const float* __restrict__ h,
                             float* __restrict__ out) {
    int b = blockIdx.x;
    int t = threadIdx.x;
    __shared__ float sp[512];
    __shared__ float red[17];
    float l = (t < NN) ? logits[b * NN + t] : -1e30f;
    float m = l;
    #pragma unroll
    for (int o = 16; o; o >>= 1) m = fmaxf(m, __shfl_xor_sync(0xffffffffu, m, o));
    if ((t & 31) == 0) red[t >> 5] = m;
    __syncthreads();
    if (t == 0) {
        float mm = red[0];
        for (int i = 1; i < 16; i++) mm = fmaxf(mm, red[i]);
        red[16] = mm;
    }
    __syncthreads();
    float mx = red[16];
    float e = (t < NN) ? expf(l - mx) : 0.f;
    sp[t] = e;
    float s = e;
    #pragma unroll
    for (int o = 16; o; o >>= 1) s += __shfl_xor_sync(0xffffffffu, s, o);
    __syncthreads();
    if ((t & 31) == 0) red[t >> 5] = s;
    __syncthreads();
    if (t == 0) {
        float ss = 0.f;
        for (int i = 0; i < 16; i++) ss += red[i];
        red[16] = 1.f / ss;
    }
    __syncthreads();
    float inv = red[16];
    const float* hb = h + (size_t)b * NN * F_;
    float acc = 0.f;
    for (int i = 0; i < NN; i++) acc += sp[i] * hb[(size_t)i * F_ + t];
    out[b * F_ + t] = acc * inv;
}

// ================= launch =================
extern "C" void kernel_launch(void* const* d_in, const int* in_sizes, int n_in,
                              void* d_out, int out_size) {
    const float* features   = (const float*)d_in[0];
    const float* eh         = (const float*)d_in[5];
    const float* Wn         = (const float*)d_in[6];
    const float* Wf         = (const float*)d_in[7];
    const float* W_U_iou    = (const float*)d_in[8];
    const float* W_U_fe_iou = (const float*)d_in[9];
    const float* b_U_fe_iou = (const float*)d_in[10];
    const float* W_U_f      = (const float*)d_in[11];
    const float* W_U_fe_f   = (const float*)d_in[12];
    const float* b_U_fe_f   = (const float*)d_in[13];
    float* out = (float*)d_out;

    float *p_en, *p_ef, *p_lg, *p_h, *p_c, *p_feiou, *p_lvl, *p_bias;
    __nv_bfloat16 *p_f2s, *p_hs, *p_wfe, *p_wu;
    cudaGetSymbolAddress((void**)&p_en,    g_enode);
    cudaGetSymbolAddress((void**)&p_ef,    g_eforw);
    cudaGetSymbolAddress((void**)&p_lg,    g_logits);
    cudaGetSymbolAddress((void**)&p_h,     g_h);
    cudaGetSymbolAddress((void**)&p_c,     g_c);
    cudaGetSymbolAddress((void**)&p_feiou, g_feiou);
    cudaGetSymbolAddress((void**)&p_lvl,   g_lvl);
    cudaGetSymbolAddress((void**)&p_bias,  g_biascat);
    cudaGetSymbolAddress((void**)&p_f2s,   g_f2s);
    cudaGetSymbolAddress((void**)&p_hs,    g_hsplit);
    cudaGetSymbolAddress((void**)&p_wfe,   g_wfe);
    cudaGetSymbolAddress((void**)&p_wu,    g_wu);

    static int smem_set = 0;
    if (!smem_set) {
        cudaFuncSetAttribute(gemm_bf16, cudaFuncAttributeMaxDynamicSharedMemorySize, GSMEM);
        smem_set = 1;
    }

    // 0) split all weights + bias
    wsplit_all<<<(2 * NC * 512 + 255) / 256, 256>>>(W_U_fe_iou, W_U_fe_f, W_U_iou, W_U_f,
                                                    p_wfe, p_wu, b_U_fe_iou, b_U_fe_f, p_bias);
    // 1) eh projections + fused attention
    eh_proj_kernel<<<(2 * B_ * F_ * 32 + 255) / 256, 256>>>(eh, Wn, Wf, p_en, p_ef);
    feat2s_kernel<<<B_ * NN, 128>>>(features, p_en, p_f2s);
    // 2) fused fe GEMM, trimmed; scatter output to (b*NN+node) rows
    {
        GP gp = { p_f2s, p_wfe, p_bias, p_feiou, B_ * NP, NP, 0, 1 };
        dim3 gridp(NC / 128, (B_ * NP + 127) / 128, 1);
        gemm_bf16<<<gridp, 256, GSMEM>>>(gp);
        GP gl = { p_f2s, p_wfe, p_bias, p_feiou, B_ * 256, 256, 255, 1 };
        dim3 gridl(1536 / 128, (B_ * 256 + 127) / 128, 1);
        gemm_bf16<<<gridl, 256, GSMEM>>>(gl);
    }
    // 3) leaves
    leaf_kernel<<<(B_ * 256 * 128 + 255) / 256, 256>>>(p_feiou, p_h, p_c, p_hs);
    // 4) levels bottom-up; split-K=3 into separate compact slices for small M
    for (int n = 1; n <= 8; n++) {
        int cnt = 1 << (8 - n);
        int start = cnt - 1;
        int rows = 2 * cnt;
        int M = B_ * rows;
        int gz = (M <= 2048) ? 3 : 1;
        GP g = { p_hs, p_wu, nullptr, p_lvl, M, rows, 2 * start + 1, 0 };
        dim3 grid(NC / 128, (M + 127) / 128, gz);
        gemm_bf16<<<grid, 256, GSMEM>>>(g);
        combine_kernel<<<(B_ * cnt * 128 + 255) / 256, 256>>>(p_lvl, p_feiou, p_h, p_c, p_hs,
                                                              start, cnt, gz, (size_t)M * NC);
    }
    // 5) output pooling
    dot_kernel<<<(B_ * NN * 32 + 255) / 256, 256>>>(p_h, p_ef, p_lg);
    final_kernel<<<B_, F_>>>(p_lg, p_h, out);
}